// round 15
// baseline (speedup 1.0000x reference)
#include <cuda_runtime.h>
#include <cuda_fp16.h>
#include <math.h>
#include <stdint.h>

// Problem constants (fixed by the dataset)
#define HEADS   8
#define OUT_F   64
#define HO      512          // HEADS * OUT_F
#define IN_F    256
#define MAXN    50048        // padded node count (multiple of 128)
#define MAXE    1600000

// ---------------- scratch (static __device__ globals, no runtime alloc) -----
__device__ __align__(16) static __half g_th[(size_t)MAXN * HO]; // 51.2 MB fp16 t (gather)
__device__ __align__(16) static float  g_w[(size_t)MAXN * HEADS]; // exp(logit)
// g_cnt and the allocation cursor adjacent so one memset clears both.
__device__ static int g_cnt[MAXN + 4];    // [MAXN] = cursor slot (cleared together)
__device__ static int g_rowptr[MAXN];     // segment start per node (arbitrary order)
__device__ static int g_cur[MAXN];
__device__ static int g_col[MAXE];

// ---------------- CSR build -------------------------------------------------
// 4 edges per thread: 4 independent atomic chains in flight.
__global__ void k_hist(const int* __restrict__ src, int E) {
    int i4 = (blockIdx.x * blockDim.x + threadIdx.x) * 4;
    if (i4 + 3 < E) {
        int4 s = *(const int4*)&src[i4];
        atomicAdd(&g_cnt[s.x], 1);
        atomicAdd(&g_cnt[s.y], 1);
        atomicAdd(&g_cnt[s.z], 1);
        atomicAdd(&g_cnt[s.w], 1);
    } else {
        for (int i = i4; i < E; ++i) atomicAdd(&g_cnt[src[i]], 1);
    }
}

// Fused segment allocation: block-local scan + one atomicAdd per block for the
// base. Segments land in block-arrival order — k_agg only needs [start,
// start+cnt) contiguous per node, not global ordering.
__global__ void k_alloc(int N) {
    __shared__ int s[1024];
    __shared__ int s_base;
    int tid = threadIdx.x;
    int i = blockIdx.x * 1024 + tid;
    int v = (i < N) ? g_cnt[i] : 0;
    s[tid] = v;
    __syncthreads();
    #pragma unroll
    for (int off = 1; off < 1024; off <<= 1) {
        int add = (tid >= off) ? s[tid - off] : 0;
        __syncthreads();
        s[tid] += add;
        __syncthreads();
    }
    if (tid == 1023) s_base = atomicAdd(&g_cnt[MAXN], s[1023]);
    __syncthreads();
    if (i < N) {
        int p = s_base + s[tid] - v;   // exclusive prefix + block base
        g_rowptr[i] = p;
        g_cur[i]    = p;
    }
}

__global__ void k_scatter(const int* __restrict__ src, const int* __restrict__ dst, int E) {
    int i4 = (blockIdx.x * blockDim.x + threadIdx.x) * 4;
    if (i4 + 3 < E) {
        int4 s = *(const int4*)&src[i4];
        int4 d = *(const int4*)&dst[i4];
        int p0 = atomicAdd(&g_cur[s.x], 1);
        int p1 = atomicAdd(&g_cur[s.y], 1);
        int p2 = atomicAdd(&g_cur[s.z], 1);
        int p3 = atomicAdd(&g_cur[s.w], 1);
        g_col[p0] = d.x;
        g_col[p1] = d.y;
        g_col[p2] = d.z;
        g_col[p3] = d.w;
    } else {
        for (int i = i4; i < E; ++i) {
            int p = atomicAdd(&g_cur[src[i]], 1);
            g_col[p] = dst[i];
        }
    }
}

// ---------------- tf32 MMA GEMM (cp.async double-buffered) ------------------
// t = x (M x 256) · Ws^T (256 x 512). BM=BN=128, BK=32, 2-stage pipeline.
// smem row-major [row][k] with pad 36 (36 mod 32 = 4 => scalar fragment loads
// conflict-free). Per K-tile, a single vectorized in-smem pass converts fp32 ->
// tf32 (cvt.rna) ONCE per element; the MMA loop then does plain LDS -> HMMA.
// (ncu R14: ALU 22.5% of issue was redundant per-fragment cvts, tensor 41%.)
// Epilogue: fp16 t store + fused per-row exp(logit) for the block's 2 heads.
#define SMPAD 36
#define ABUF  4608            // 128*36 floats per stage
#define GEMM_SMEM ((2*ABUF*2 + 128 + 256) * 4)   // 75264 B

__device__ __forceinline__ void cp16(void* smem_dst, const void* gsrc, int nbytes) {
    uint32_t s = (uint32_t)__cvta_generic_to_shared(smem_dst);
    asm volatile("cp.async.ca.shared.global [%0], [%1], 16, %2;\n"
                 :: "r"(s), "l"(gsrc), "r"(nbytes));
}

__device__ __forceinline__ float rnaf(float x) {
    uint32_t u;
    asm("cvt.rna.tf32.f32 %0, %1;" : "=r"(u) : "f"(x));
    return __uint_as_float(u);
}

__global__ __launch_bounds__(256) void k_gemm(const float* __restrict__ A,
                                              const float* __restrict__ B,
                                              const float* __restrict__ As_in,
                                              int M) {
    extern __shared__ float dyn[];
    float* pA      = dyn;                 // [2][128][SMPAD]
    float* pB      = dyn + 2 * ABUF;      // [2][128][SMPAD]
    float* s_ar    = dyn + 4 * ABUF;      // [128]
    float* s_logit = s_ar + 128;          // [128][2]

    int tid  = threadIdx.x;
    int lane = tid & 31;
    int warp = tid >> 5;
    int wm   = (warp & 1) * 64;
    int wn   = (warp >> 1) * 32;
    int m0   = blockIdx.x * 128;
    int n0   = blockIdx.y * 128;

    if (tid < 128) {
        int c = n0 + tid;
        s_ar[tid] = As_in[(c >> 6) * 128 + 64 + (c & 63)];
    }
    s_logit[tid] = 0.f;   // 256 floats total, 256 threads

    float acc[4][4][4];
    #pragma unroll
    for (int mi = 0; mi < 4; ++mi)
        #pragma unroll
        for (int ni = 0; ni < 4; ++ni)
            #pragma unroll
            for (int j = 0; j < 4; ++j) acc[mi][ni][j] = 0.f;

    // stage issue: 128 rows x 32 floats for A and B = 1024 16B chunks each
    #define ISSUE(k0, buf)                                                     \
        do {                                                                   \
            _Pragma("unroll")                                                  \
            for (int r = 0; r < 4; ++r) {                                      \
                int id  = r * 256 + tid;                                       \
                int row = id >> 3;                                             \
                int c4  = (id & 7) * 4;                                        \
                cp16(&pA[(buf) * ABUF + row * SMPAD + c4],                     \
                     &A[(size_t)(m0 + row) * IN_F + (k0) + c4],                \
                     (m0 + row < M) ? 16 : 0);                                 \
                cp16(&pB[(buf) * ABUF + row * SMPAD + c4],                     \
                     &B[(size_t)(n0 + row) * IN_F + (k0) + c4], 16);           \
            }                                                                  \
            asm volatile("cp.async.commit_group;\n");                          \
        } while (0)

    ISSUE(0, 0);

    int lr = lane >> 2;   // 0..7
    int lc = lane & 3;    // 0..3

    for (int k0i = 0; k0i < 8; ++k0i) {
        int cur = k0i & 1;
        if (k0i < 7) {
            ISSUE((k0i + 1) * 32, cur ^ 1);
            asm volatile("cp.async.wait_group 1;\n");
        } else {
            asm volatile("cp.async.wait_group 0;\n");
        }
        __syncthreads();

        float* Ab = pA + cur * ABUF;
        float* Bb = pB + cur * ABUF;

        // one-shot tf32 conversion pass (vectorized, same mapping as ISSUE)
        #pragma unroll
        for (int r = 0; r < 4; ++r) {
            int id  = r * 256 + tid;
            int row = id >> 3;
            int c4  = (id & 7) * 4;
            float4* ap = (float4*)&Ab[row * SMPAD + c4];
            float4  av = *ap;
            *ap = make_float4(rnaf(av.x), rnaf(av.y), rnaf(av.z), rnaf(av.w));
            float4* bp = (float4*)&Bb[row * SMPAD + c4];
            float4  bv = *bp;
            *bp = make_float4(rnaf(bv.x), rnaf(bv.y), rnaf(bv.z), rnaf(bv.w));
        }
        __syncthreads();

        #pragma unroll
        for (int kk = 0; kk < 32; kk += 8) {
            uint32_t afr[4][4];
            uint32_t bfr[4][2];
            #pragma unroll
            for (int mi = 0; mi < 4; ++mi) {
                int rb = wm + mi * 16;
                afr[mi][0] = __float_as_uint(Ab[(rb + lr    ) * SMPAD + kk + lc    ]);
                afr[mi][1] = __float_as_uint(Ab[(rb + lr + 8) * SMPAD + kk + lc    ]);
                afr[mi][2] = __float_as_uint(Ab[(rb + lr    ) * SMPAD + kk + lc + 4]);
                afr[mi][3] = __float_as_uint(Ab[(rb + lr + 8) * SMPAD + kk + lc + 4]);
            }
            #pragma unroll
            for (int ni = 0; ni < 4; ++ni) {
                int nb = wn + ni * 8;
                bfr[ni][0] = __float_as_uint(Bb[(nb + lr) * SMPAD + kk + lc    ]);
                bfr[ni][1] = __float_as_uint(Bb[(nb + lr) * SMPAD + kk + lc + 4]);
            }
            #pragma unroll
            for (int mi = 0; mi < 4; ++mi)
                #pragma unroll
                for (int ni = 0; ni < 4; ++ni) {
                    asm volatile(
                        "mma.sync.aligned.m16n8k8.row.col.f32.tf32.tf32.f32 "
                        "{%0,%1,%2,%3}, {%4,%5,%6,%7}, {%8,%9}, {%0,%1,%2,%3};\n"
                        : "+f"(acc[mi][ni][0]), "+f"(acc[mi][ni][1]),
                          "+f"(acc[mi][ni][2]), "+f"(acc[mi][ni][3])
                        : "r"(afr[mi][0]), "r"(afr[mi][1]),
                          "r"(afr[mi][2]), "r"(afr[mi][3]),
                          "r"(bfr[ni][0]), "r"(bfr[ni][1]));
                }
        }
        __syncthreads();
    }

    // epilogue: fp16 t store + block-local logit reduction
    int head_local = warp >> 2;   // warps 0-3 -> head 0 of block; 4-7 -> head 1
    #pragma unroll
    for (int mi = 0; mi < 4; ++mi) {
        int r0 = m0 + wm + mi * 16 + lr;
        int r1 = r0 + 8;
        float p0 = 0.f, p1 = 0.f;
        #pragma unroll
        for (int ni = 0; ni < 4; ++ni) {
            int cl = wn + ni * 8 + lc * 2;    // block-local col
            int c  = n0 + cl;
            p0 = fmaf(acc[mi][ni][0], s_ar[cl], fmaf(acc[mi][ni][1], s_ar[cl + 1], p0));
            p1 = fmaf(acc[mi][ni][2], s_ar[cl], fmaf(acc[mi][ni][3], s_ar[cl + 1], p1));
            if (r0 < M)
                *(__half2*)&g_th[(size_t)r0 * HO + c] =
                    __floats2half2_rn(acc[mi][ni][0], acc[mi][ni][1]);
            if (r1 < M)
                *(__half2*)&g_th[(size_t)r1 * HO + c] =
                    __floats2half2_rn(acc[mi][ni][2], acc[mi][ni][3]);
        }
        atomicAdd(&s_logit[(wm + mi * 16 + lr    ) * 2 + head_local], p0);
        atomicAdd(&s_logit[(wm + mi * 16 + lr + 8) * 2 + head_local], p1);
    }
    __syncthreads();

    if (tid < 128 && m0 + tid < M) {
        int hb = blockIdx.y * 2;
        g_w[(size_t)(m0 + tid) * HEADS + hb    ] = expf(s_logit[tid * 2 + 0]);
        g_w[(size_t)(m0 + tid) * HEADS + hb + 1] = expf(s_logit[tid * 2 + 1]);
    }
}

// ---------------- aggregation + ELU (fp16 gather, post-normalize) -----------
// One block (128 thr) per node — the empirically fastest structure (R8).
// Thread j owns out[n, 4j..4j+3]; head h = j/16. Column indices staged through
// shared memory with __syncthreads. Segment = [rowptr[n], rowptr[n]+cnt[n]).
// h[n] = (sum_e w_d * t_d) / (sum_e w_d): softmax normalization at the end
// (Al and the max-shift cancel in the ratio).
__global__ __launch_bounds__(128) void k_agg(float* __restrict__ out) {
    __shared__ int s_col[128];

    int n   = blockIdx.x;
    int tid = threadIdx.x;
    int rs  = g_rowptr[n];
    int re  = rs + g_cnt[n];
    int h   = tid >> 4;

    if (re == rs) {  // no outgoing edges: out = elu(0) = 0
        *(float4*)&out[(size_t)n * HO + tid * 4] = make_float4(0.f, 0.f, 0.f, 0.f);
        return;
    }

    float  ws  = 0.f;
    float4 acc = make_float4(0.f, 0.f, 0.f, 0.f);
    const uint2* th2 = (const uint2*)g_th;   // 8 bytes = 4 fp16 per thread

    for (int base = rs; base < re; base += 128) {
        int nload = min(128, re - base);
        __syncthreads();
        if (tid < nload) s_col[tid] = __ldg(&g_col[base + tid]);
        __syncthreads();
        #pragma unroll 4
        for (int e = 0; e < nload; ++e) {
            int d = s_col[e];
            float wv = __ldg(&g_w[(size_t)d * 8 + h]);
            ws += wv;
            uint2 v = th2[(size_t)d * 128 + tid];   // coalesced 1KB row gather
            float2 f0 = __half22float2(*(__half2*)&v.x);
            float2 f1 = __half22float2(*(__half2*)&v.y);
            acc.x = fmaf(wv, f0.x, acc.x);
            acc.y = fmaf(wv, f0.y, acc.y);
            acc.z = fmaf(wv, f1.x, acc.z);
            acc.w = fmaf(wv, f1.y, acc.w);
        }
    }

    float inv = 1.f / ws;
    acc.x *= inv; acc.y *= inv; acc.z *= inv; acc.w *= inv;

    float4 r;
    r.x = acc.x > 0.f ? acc.x : expm1f(acc.x);
    r.y = acc.y > 0.f ? acc.y : expm1f(acc.y);
    r.z = acc.z > 0.f ? acc.z : expm1f(acc.z);
    r.w = acc.w > 0.f ? acc.w : expm1f(acc.w);
    __stcs((float4*)&out[(size_t)n * HO + tid * 4], r);  // stream out, keep t in L2
}

// ---------------- launch ----------------------------------------------------
extern "C" void kernel_launch(void* const* d_in, const int* in_sizes, int n_in,
                              void* d_out, int out_size) {
    const float* x   = (const float*)d_in[0];
    const int*   src = (const int*)  d_in[1];
    const int*   dst = (const int*)  d_in[2];
    const float* Ws  = (const float*)d_in[3];
    const float* As  = (const float*)d_in[4];
    float* out = (float*)d_out;

    int N = in_sizes[0] / IN_F;   // 50000
    int E = in_sizes[1];          // 1600000

    // CSR build (by src): memset(cnt+cursor) -> hist -> fused alloc -> scatter
    void* cnt_ptr = nullptr;
    cudaGetSymbolAddress(&cnt_ptr, g_cnt);
    cudaMemsetAsync(cnt_ptr, 0, sizeof(int) * (MAXN + 4));
    int tE = (E + 3) / 4;
    k_hist<<<(tE + 255) / 256, 256>>>(src, E);
    k_alloc<<<(N + 1023) / 1024, 1024>>>(N);
    k_scatter<<<(tE + 255) / 256, 256>>>(src, dst, E);

    // fused: feature transform (fp16 t) + attention weights exp(logit)
    cudaFuncSetAttribute(k_gemm, cudaFuncAttributeMaxDynamicSharedMemorySize,
                         GEMM_SMEM);
    dim3 gg((N + 127) / 128, HO / 128);
    k_gemm<<<gg, 256, GEMM_SMEM>>>(x, Ws, As, N);

    // softmax-weighted aggregation + ELU (one node per block)
    k_agg<<<N, 128>>>(out);
}

// round 16
// speedup vs baseline: 1.0636x; 1.0636x over previous
#include <cuda_runtime.h>
#include <cuda_fp16.h>
#include <math.h>
#include <stdint.h>

// Problem constants (fixed by the dataset)
#define HEADS   8
#define OUT_F   64
#define HO      512          // HEADS * OUT_F
#define IN_F    256
#define MAXN    50048        // padded node count (multiple of 128)
#define MAXE    1600000

// ---------------- scratch (static __device__ globals, no runtime alloc) -----
__device__ __align__(16) static __half g_th[(size_t)MAXN * HO]; // 51.2 MB fp16 t (gather)
__device__ __align__(16) static float  g_w[(size_t)MAXN * HEADS]; // exp(logit)
__device__ __align__(16) static float  g_Bt[HO * IN_F];         // 512 KB tf32-rounded Ws
// g_cnt and the allocation cursor adjacent so one memset clears both.
__device__ static int g_cnt[MAXN + 4];    // [MAXN] = cursor slot (cleared together)
__device__ static int g_rowptr[MAXN];     // segment start per node (arbitrary order)
__device__ static int g_cur[MAXN];
__device__ static int g_col[MAXE];

// ---------------- CSR build -------------------------------------------------
// 4 edges per thread: 4 independent atomic chains in flight.
__global__ void k_hist(const int* __restrict__ src, int E) {
    int i4 = (blockIdx.x * blockDim.x + threadIdx.x) * 4;
    if (i4 + 3 < E) {
        int4 s = *(const int4*)&src[i4];
        atomicAdd(&g_cnt[s.x], 1);
        atomicAdd(&g_cnt[s.y], 1);
        atomicAdd(&g_cnt[s.z], 1);
        atomicAdd(&g_cnt[s.w], 1);
    } else {
        for (int i = i4; i < E; ++i) atomicAdd(&g_cnt[src[i]], 1);
    }
}

// Fused segment allocation: block-local scan + one atomicAdd per block for the
// base. Segments land in block-arrival order — k_agg only needs [start,
// start+cnt) contiguous per node, not global ordering.
__global__ void k_alloc(int N) {
    __shared__ int s[1024];
    __shared__ int s_base;
    int tid = threadIdx.x;
    int i = blockIdx.x * 1024 + tid;
    int v = (i < N) ? g_cnt[i] : 0;
    s[tid] = v;
    __syncthreads();
    #pragma unroll
    for (int off = 1; off < 1024; off <<= 1) {
        int add = (tid >= off) ? s[tid - off] : 0;
        __syncthreads();
        s[tid] += add;
        __syncthreads();
    }
    if (tid == 1023) s_base = atomicAdd(&g_cnt[MAXN], s[1023]);
    __syncthreads();
    if (i < N) {
        int p = s_base + s[tid] - v;   // exclusive prefix + block base
        g_rowptr[i] = p;
        g_cur[i]    = p;
    }
}

__global__ void k_scatter(const int* __restrict__ src, const int* __restrict__ dst, int E) {
    int i4 = (blockIdx.x * blockDim.x + threadIdx.x) * 4;
    if (i4 + 3 < E) {
        int4 s = *(const int4*)&src[i4];
        int4 d = *(const int4*)&dst[i4];
        int p0 = atomicAdd(&g_cur[s.x], 1);
        int p1 = atomicAdd(&g_cur[s.y], 1);
        int p2 = atomicAdd(&g_cur[s.z], 1);
        int p3 = atomicAdd(&g_cur[s.w], 1);
        g_col[p0] = d.x;
        g_col[p1] = d.y;
        g_col[p2] = d.z;
        g_col[p3] = d.w;
    } else {
        for (int i = i4; i < E; ++i) {
            int p = atomicAdd(&g_cur[src[i]], 1);
            g_col[p] = dst[i];
        }
    }
}

// ---------------- tf32 helpers ----------------------------------------------
__device__ __forceinline__ uint32_t rna(float x) {
    uint32_t u;
    asm("cvt.rna.tf32.f32 %0, %1;" : "=r"(u) : "f"(x));
    return u;
}

// Pre-round Ws (512x256, 512 KB) to tf32 once — every GEMM block re-reads B,
// so this kills the bfr cvts in the hot loop with no added smem traffic.
__global__ void k_roundB(const float* __restrict__ B) {
    int i4 = (blockIdx.x * blockDim.x + threadIdx.x) * 4;
    float4 v = *(const float4*)&B[i4];
    float4 r;
    r.x = __uint_as_float(rna(v.x));
    r.y = __uint_as_float(rna(v.y));
    r.z = __uint_as_float(rna(v.z));
    r.w = __uint_as_float(rna(v.w));
    *(float4*)&g_Bt[i4] = r;
}

// ---------------- tf32 MMA GEMM (cp.async double-buffered) ------------------
// t = x (M x 256) · Ws^T (256 x 512). BM=BN=128, BK=32, 2-stage pipeline.
// smem row-major [row][k] with pad 36 (36 mod 32 = 4 => scalar fragment loads
// conflict-free). A fragments rna-converted at register load (R13 form — the
// in-smem conversion pass regressed: smem crossbar was co-binding). B comes
// pre-rounded from k_roundB, so B fragment loads are plain LDS.
// Epilogue: fp16 t store + fused per-row exp(logit) for the block's 2 heads.
#define SMPAD 36
#define ABUF  4608            // 128*36 floats per stage
#define GEMM_SMEM ((2*ABUF*2 + 128 + 256) * 4)   // 75264 B

__device__ __forceinline__ void cp16(void* smem_dst, const void* gsrc, int nbytes) {
    uint32_t s = (uint32_t)__cvta_generic_to_shared(smem_dst);
    asm volatile("cp.async.ca.shared.global [%0], [%1], 16, %2;\n"
                 :: "r"(s), "l"(gsrc), "r"(nbytes));
}

__global__ __launch_bounds__(256) void k_gemm(const float* __restrict__ A,
                                              const float* __restrict__ As_in,
                                              int M) {
    extern __shared__ float dyn[];
    float* pA      = dyn;                 // [2][128][SMPAD]
    float* pB      = dyn + 2 * ABUF;      // [2][128][SMPAD]
    float* s_ar    = dyn + 4 * ABUF;      // [128]
    float* s_logit = s_ar + 128;          // [128][2]

    int tid  = threadIdx.x;
    int lane = tid & 31;
    int warp = tid >> 5;
    int wm   = (warp & 1) * 64;
    int wn   = (warp >> 1) * 32;
    int m0   = blockIdx.x * 128;
    int n0   = blockIdx.y * 128;

    if (tid < 128) {
        int c = n0 + tid;
        s_ar[tid] = As_in[(c >> 6) * 128 + 64 + (c & 63)];
    }
    s_logit[tid] = 0.f;   // 256 floats total, 256 threads

    float acc[4][4][4];
    #pragma unroll
    for (int mi = 0; mi < 4; ++mi)
        #pragma unroll
        for (int ni = 0; ni < 4; ++ni)
            #pragma unroll
            for (int j = 0; j < 4; ++j) acc[mi][ni][j] = 0.f;

    // stage issue: 128 rows x 32 floats for A and B = 1024 16B chunks each
    #define ISSUE(k0, buf)                                                     \
        do {                                                                   \
            _Pragma("unroll")                                                  \
            for (int r = 0; r < 4; ++r) {                                      \
                int id  = r * 256 + tid;                                       \
                int row = id >> 3;                                             \
                int c4  = (id & 7) * 4;                                        \
                cp16(&pA[(buf) * ABUF + row * SMPAD + c4],                     \
                     &A[(size_t)(m0 + row) * IN_F + (k0) + c4],                \
                     (m0 + row < M) ? 16 : 0);                                 \
                cp16(&pB[(buf) * ABUF + row * SMPAD + c4],                     \
                     &g_Bt[(size_t)(n0 + row) * IN_F + (k0) + c4], 16);        \
            }                                                                  \
            asm volatile("cp.async.commit_group;\n");                          \
        } while (0)

    ISSUE(0, 0);

    int lr = lane >> 2;   // 0..7
    int lc = lane & 3;    // 0..3

    for (int k0i = 0; k0i < 8; ++k0i) {
        int cur = k0i & 1;
        if (k0i < 7) {
            ISSUE((k0i + 1) * 32, cur ^ 1);
            asm volatile("cp.async.wait_group 1;\n");
        } else {
            asm volatile("cp.async.wait_group 0;\n");
        }
        __syncthreads();

        const float* Ab = pA + cur * ABUF;
        const float* Bb = pB + cur * ABUF;
        #pragma unroll
        for (int kk = 0; kk < 32; kk += 8) {
            uint32_t afr[4][4];
            uint32_t bfr[4][2];
            #pragma unroll
            for (int mi = 0; mi < 4; ++mi) {
                int rb = wm + mi * 16;
                afr[mi][0] = rna(Ab[(rb + lr    ) * SMPAD + kk + lc    ]);
                afr[mi][1] = rna(Ab[(rb + lr + 8) * SMPAD + kk + lc    ]);
                afr[mi][2] = rna(Ab[(rb + lr    ) * SMPAD + kk + lc + 4]);
                afr[mi][3] = rna(Ab[(rb + lr + 8) * SMPAD + kk + lc + 4]);
            }
            #pragma unroll
            for (int ni = 0; ni < 4; ++ni) {
                int nb = wn + ni * 8;
                bfr[ni][0] = __float_as_uint(Bb[(nb + lr) * SMPAD + kk + lc    ]);
                bfr[ni][1] = __float_as_uint(Bb[(nb + lr) * SMPAD + kk + lc + 4]);
            }
            #pragma unroll
            for (int mi = 0; mi < 4; ++mi)
                #pragma unroll
                for (int ni = 0; ni < 4; ++ni) {
                    asm volatile(
                        "mma.sync.aligned.m16n8k8.row.col.f32.tf32.tf32.f32 "
                        "{%0,%1,%2,%3}, {%4,%5,%6,%7}, {%8,%9}, {%0,%1,%2,%3};\n"
                        : "+f"(acc[mi][ni][0]), "+f"(acc[mi][ni][1]),
                          "+f"(acc[mi][ni][2]), "+f"(acc[mi][ni][3])
                        : "r"(afr[mi][0]), "r"(afr[mi][1]),
                          "r"(afr[mi][2]), "r"(afr[mi][3]),
                          "r"(bfr[ni][0]), "r"(bfr[ni][1]));
                }
        }
        __syncthreads();
    }

    // epilogue: fp16 t store + block-local logit reduction
    int head_local = warp >> 2;   // warps 0-3 -> head 0 of block; 4-7 -> head 1
    #pragma unroll
    for (int mi = 0; mi < 4; ++mi) {
        int r0 = m0 + wm + mi * 16 + lr;
        int r1 = r0 + 8;
        float p0 = 0.f, p1 = 0.f;
        #pragma unroll
        for (int ni = 0; ni < 4; ++ni) {
            int cl = wn + ni * 8 + lc * 2;    // block-local col
            int c  = n0 + cl;
            p0 = fmaf(acc[mi][ni][0], s_ar[cl], fmaf(acc[mi][ni][1], s_ar[cl + 1], p0));
            p1 = fmaf(acc[mi][ni][2], s_ar[cl], fmaf(acc[mi][ni][3], s_ar[cl + 1], p1));
            if (r0 < M)
                *(__half2*)&g_th[(size_t)r0 * HO + c] =
                    __floats2half2_rn(acc[mi][ni][0], acc[mi][ni][1]);
            if (r1 < M)
                *(__half2*)&g_th[(size_t)r1 * HO + c] =
                    __floats2half2_rn(acc[mi][ni][2], acc[mi][ni][3]);
        }
        atomicAdd(&s_logit[(wm + mi * 16 + lr    ) * 2 + head_local], p0);
        atomicAdd(&s_logit[(wm + mi * 16 + lr + 8) * 2 + head_local], p1);
    }
    __syncthreads();

    if (tid < 128 && m0 + tid < M) {
        int hb = blockIdx.y * 2;
        g_w[(size_t)(m0 + tid) * HEADS + hb    ] = expf(s_logit[tid * 2 + 0]);
        g_w[(size_t)(m0 + tid) * HEADS + hb + 1] = expf(s_logit[tid * 2 + 1]);
    }
}

// ---------------- aggregation + ELU (fp16 gather, post-normalize) -----------
// One block (128 thr) per node — the empirically fastest structure (R8).
// Thread j owns out[n, 4j..4j+3]; head h = j/16. Column indices staged through
// shared memory with __syncthreads. Segment = [rowptr[n], rowptr[n]+cnt[n]).
// h[n] = (sum_e w_d * t_d) / (sum_e w_d): softmax normalization at the end
// (Al and the max-shift cancel in the ratio).
__global__ __launch_bounds__(128) void k_agg(float* __restrict__ out) {
    __shared__ int s_col[128];

    int n   = blockIdx.x;
    int tid = threadIdx.x;
    int rs  = g_rowptr[n];
    int re  = rs + g_cnt[n];
    int h   = tid >> 4;

    if (re == rs) {  // no outgoing edges: out = elu(0) = 0
        *(float4*)&out[(size_t)n * HO + tid * 4] = make_float4(0.f, 0.f, 0.f, 0.f);
        return;
    }

    float  ws  = 0.f;
    float4 acc = make_float4(0.f, 0.f, 0.f, 0.f);
    const uint2* th2 = (const uint2*)g_th;   // 8 bytes = 4 fp16 per thread

    for (int base = rs; base < re; base += 128) {
        int nload = min(128, re - base);
        __syncthreads();
        if (tid < nload) s_col[tid] = __ldg(&g_col[base + tid]);
        __syncthreads();
        #pragma unroll 4
        for (int e = 0; e < nload; ++e) {
            int d = s_col[e];
            float wv = __ldg(&g_w[(size_t)d * 8 + h]);
            ws += wv;
            uint2 v = th2[(size_t)d * 128 + tid];   // coalesced 1KB row gather
            float2 f0 = __half22float2(*(__half2*)&v.x);
            float2 f1 = __half22float2(*(__half2*)&v.y);
            acc.x = fmaf(wv, f0.x, acc.x);
            acc.y = fmaf(wv, f0.y, acc.y);
            acc.z = fmaf(wv, f1.x, acc.z);
            acc.w = fmaf(wv, f1.y, acc.w);
        }
    }

    float inv = 1.f / ws;
    acc.x *= inv; acc.y *= inv; acc.z *= inv; acc.w *= inv;

    float4 r;
    r.x = acc.x > 0.f ? acc.x : expm1f(acc.x);
    r.y = acc.y > 0.f ? acc.y : expm1f(acc.y);
    r.z = acc.z > 0.f ? acc.z : expm1f(acc.z);
    r.w = acc.w > 0.f ? acc.w : expm1f(acc.w);
    __stcs((float4*)&out[(size_t)n * HO + tid * 4], r);  // stream out, keep t in L2
}

// ---------------- launch ----------------------------------------------------
extern "C" void kernel_launch(void* const* d_in, const int* in_sizes, int n_in,
                              void* d_out, int out_size) {
    const float* x   = (const float*)d_in[0];
    const int*   src = (const int*)  d_in[1];
    const int*   dst = (const int*)  d_in[2];
    const float* Ws  = (const float*)d_in[3];
    const float* As  = (const float*)d_in[4];
    float* out = (float*)d_out;

    int N = in_sizes[0] / IN_F;   // 50000
    int E = in_sizes[1];          // 1600000

    // CSR build (by src): memset(cnt+cursor) -> hist -> fused alloc -> scatter
    void* cnt_ptr = nullptr;
    cudaGetSymbolAddress(&cnt_ptr, g_cnt);
    cudaMemsetAsync(cnt_ptr, 0, sizeof(int) * (MAXN + 4));
    int tE = (E + 3) / 4;
    k_hist<<<(tE + 255) / 256, 256>>>(src, E);
    k_alloc<<<(N + 1023) / 1024, 1024>>>(N);
    k_scatter<<<(tE + 255) / 256, 256>>>(src, dst, E);

    // pre-round Ws to tf32 (512 KB, one pass), then fused GEMM + exp(logit)
    k_roundB<<<(HO * IN_F / 4 + 255) / 256, 256>>>(Ws);
    cudaFuncSetAttribute(k_gemm, cudaFuncAttributeMaxDynamicSharedMemorySize,
                         GEMM_SMEM);
    dim3 gg((N + 127) / 128, HO / 128);
    k_gemm<<<gg, 256, GEMM_SMEM>>>(x, As, N);

    // softmax-weighted aggregation + ELU (one node per block)
    k_agg<<<N, 128>>>(out);
}

// round 17
// speedup vs baseline: 1.1031x; 1.0372x over previous
#include <cuda_runtime.h>
#include <cuda_fp16.h>
#include <math.h>
#include <stdint.h>

// Problem constants (fixed by the dataset)
#define HEADS   8
#define OUT_F   64
#define HO      512          // HEADS * OUT_F
#define IN_F    256
#define MAXN    50048        // padded node count (multiple of 128)
#define MAXE    1600000

// ---------------- scratch (static __device__ globals, no runtime alloc) -----
__device__ __align__(16) static __half g_th[(size_t)MAXN * HO]; // 51.2 MB fp16 t (gather)
__device__ __align__(16) static float  g_w[(size_t)MAXN * HEADS]; // exp(logit)
__device__ __align__(16) static float  g_Bt[HO * IN_F];         // 512 KB tf32-rounded Ws
// g_cnt and the allocation cursor adjacent so one memset clears both.
__device__ static int g_cnt[MAXN + 4];    // [MAXN] = cursor slot (cleared together)
__device__ static int g_rowptr[MAXN];     // segment start per node (arbitrary order)
__device__ static int g_cur[MAXN];
__device__ static int g_col[MAXE];

// ---------------- CSR build -------------------------------------------------
// 4 edges per thread: 4 independent atomic chains in flight.
__global__ void k_hist(const int* __restrict__ src, int E) {
    int i4 = (blockIdx.x * blockDim.x + threadIdx.x) * 4;
    if (i4 + 3 < E) {
        int4 s = *(const int4*)&src[i4];
        atomicAdd(&g_cnt[s.x], 1);
        atomicAdd(&g_cnt[s.y], 1);
        atomicAdd(&g_cnt[s.z], 1);
        atomicAdd(&g_cnt[s.w], 1);
    } else {
        for (int i = i4; i < E; ++i) atomicAdd(&g_cnt[src[i]], 1);
    }
}

// Fused segment allocation: block-local scan + one atomicAdd per block for the
// base. Segments land in block-arrival order — k_agg only needs [start,
// start+cnt) contiguous per node, not global ordering.
__global__ void k_alloc(int N) {
    __shared__ int s[1024];
    __shared__ int s_base;
    int tid = threadIdx.x;
    int i = blockIdx.x * 1024 + tid;
    int v = (i < N) ? g_cnt[i] : 0;
    s[tid] = v;
    __syncthreads();
    #pragma unroll
    for (int off = 1; off < 1024; off <<= 1) {
        int add = (tid >= off) ? s[tid - off] : 0;
        __syncthreads();
        s[tid] += add;
        __syncthreads();
    }
    if (tid == 1023) s_base = atomicAdd(&g_cnt[MAXN], s[1023]);
    __syncthreads();
    if (i < N) {
        int p = s_base + s[tid] - v;   // exclusive prefix + block base
        g_rowptr[i] = p;
        g_cur[i]    = p;
    }
}

__global__ void k_scatter(const int* __restrict__ src, const int* __restrict__ dst, int E) {
    int i4 = (blockIdx.x * blockDim.x + threadIdx.x) * 4;
    if (i4 + 3 < E) {
        int4 s = *(const int4*)&src[i4];
        int4 d = *(const int4*)&dst[i4];
        int p0 = atomicAdd(&g_cur[s.x], 1);
        int p1 = atomicAdd(&g_cur[s.y], 1);
        int p2 = atomicAdd(&g_cur[s.z], 1);
        int p3 = atomicAdd(&g_cur[s.w], 1);
        g_col[p0] = d.x;
        g_col[p1] = d.y;
        g_col[p2] = d.z;
        g_col[p3] = d.w;
    } else {
        for (int i = i4; i < E; ++i) {
            int p = atomicAdd(&g_cur[src[i]], 1);
            g_col[p] = dst[i];
        }
    }
}

// ---------------- tf32 helpers ----------------------------------------------
__device__ __forceinline__ uint32_t rna(float x) {
    uint32_t u;
    asm("cvt.rna.tf32.f32 %0, %1;" : "=r"(u) : "f"(x));
    return u;
}

// Pre-round Ws (512x256, 512 KB) to tf32 once — every GEMM block re-reads B,
// so this kills the bfr cvts in the hot loop with no added smem traffic.
__global__ void k_roundB(const float* __restrict__ B) {
    int i4 = (blockIdx.x * blockDim.x + threadIdx.x) * 4;
    float4 v = *(const float4*)&B[i4];
    float4 r;
    r.x = __uint_as_float(rna(v.x));
    r.y = __uint_as_float(rna(v.y));
    r.z = __uint_as_float(rna(v.z));
    r.w = __uint_as_float(rna(v.w));
    *(float4*)&g_Bt[i4] = r;
}

// ---------------- tf32 MMA GEMM (cp.async double-buffered) ------------------
// t = x (M x 256) · Ws^T (256 x 512). BM=BN=128, BK=32, 2-stage pipeline.
// smem row-major [row][k] with pad 36 (36 mod 32 = 4 => scalar fragment loads
// conflict-free). A fragments rna-converted at register load (R13 form — the
// in-smem conversion pass regressed: smem crossbar was co-binding). B comes
// pre-rounded from k_roundB, so B fragment loads are plain LDS.
// Epilogue: fp16 t store + fused per-row exp(logit) for the block's 2 heads.
#define SMPAD 36
#define ABUF  4608            // 128*36 floats per stage
#define GEMM_SMEM ((2*ABUF*2 + 128 + 256) * 4)   // 75264 B

__device__ __forceinline__ void cp16(void* smem_dst, const void* gsrc, int nbytes) {
    uint32_t s = (uint32_t)__cvta_generic_to_shared(smem_dst);
    asm volatile("cp.async.ca.shared.global [%0], [%1], 16, %2;\n"
                 :: "r"(s), "l"(gsrc), "r"(nbytes));
}

__global__ __launch_bounds__(256) void k_gemm(const float* __restrict__ A,
                                              const float* __restrict__ As_in,
                                              int M) {
    extern __shared__ float dyn[];
    float* pA      = dyn;                 // [2][128][SMPAD]
    float* pB      = dyn + 2 * ABUF;      // [2][128][SMPAD]
    float* s_ar    = dyn + 4 * ABUF;      // [128]
    float* s_logit = s_ar + 128;          // [128][2]

    int tid  = threadIdx.x;
    int lane = tid & 31;
    int warp = tid >> 5;
    int wm   = (warp & 1) * 64;
    int wn   = (warp >> 1) * 32;
    int m0   = blockIdx.x * 128;
    int n0   = blockIdx.y * 128;

    if (tid < 128) {
        int c = n0 + tid;
        s_ar[tid] = As_in[(c >> 6) * 128 + 64 + (c & 63)];
    }
    s_logit[tid] = 0.f;   // 256 floats total, 256 threads

    float acc[4][4][4];
    #pragma unroll
    for (int mi = 0; mi < 4; ++mi)
        #pragma unroll
        for (int ni = 0; ni < 4; ++ni)
            #pragma unroll
            for (int j = 0; j < 4; ++j) acc[mi][ni][j] = 0.f;

    // stage issue: 128 rows x 32 floats for A and B = 1024 16B chunks each
    #define ISSUE(k0, buf)                                                     \
        do {                                                                   \
            _Pragma("unroll")                                                  \
            for (int r = 0; r < 4; ++r) {                                      \
                int id  = r * 256 + tid;                                       \
                int row = id >> 3;                                             \
                int c4  = (id & 7) * 4;                                        \
                cp16(&pA[(buf) * ABUF + row * SMPAD + c4],                     \
                     &A[(size_t)(m0 + row) * IN_F + (k0) + c4],                \
                     (m0 + row < M) ? 16 : 0);                                 \
                cp16(&pB[(buf) * ABUF + row * SMPAD + c4],                     \
                     &g_Bt[(size_t)(n0 + row) * IN_F + (k0) + c4], 16);        \
            }                                                                  \
            asm volatile("cp.async.commit_group;\n");                          \
        } while (0)

    ISSUE(0, 0);

    int lr = lane >> 2;   // 0..7
    int lc = lane & 3;    // 0..3

    for (int k0i = 0; k0i < 8; ++k0i) {
        int cur = k0i & 1;
        if (k0i < 7) {
            ISSUE((k0i + 1) * 32, cur ^ 1);
            asm volatile("cp.async.wait_group 1;\n");
        } else {
            asm volatile("cp.async.wait_group 0;\n");
        }
        __syncthreads();

        const float* Ab = pA + cur * ABUF;
        const float* Bb = pB + cur * ABUF;
        #pragma unroll
        for (int kk = 0; kk < 32; kk += 8) {
            uint32_t afr[4][4];
            uint32_t bfr[4][2];
            #pragma unroll
            for (int mi = 0; mi < 4; ++mi) {
                int rb = wm + mi * 16;
                afr[mi][0] = rna(Ab[(rb + lr    ) * SMPAD + kk + lc    ]);
                afr[mi][1] = rna(Ab[(rb + lr + 8) * SMPAD + kk + lc    ]);
                afr[mi][2] = rna(Ab[(rb + lr    ) * SMPAD + kk + lc + 4]);
                afr[mi][3] = rna(Ab[(rb + lr + 8) * SMPAD + kk + lc + 4]);
            }
            #pragma unroll
            for (int ni = 0; ni < 4; ++ni) {
                int nb = wn + ni * 8;
                bfr[ni][0] = __float_as_uint(Bb[(nb + lr) * SMPAD + kk + lc    ]);
                bfr[ni][1] = __float_as_uint(Bb[(nb + lr) * SMPAD + kk + lc + 4]);
            }
            #pragma unroll
            for (int mi = 0; mi < 4; ++mi)
                #pragma unroll
                for (int ni = 0; ni < 4; ++ni) {
                    asm volatile(
                        "mma.sync.aligned.m16n8k8.row.col.f32.tf32.tf32.f32 "
                        "{%0,%1,%2,%3}, {%4,%5,%6,%7}, {%8,%9}, {%0,%1,%2,%3};\n"
                        : "+f"(acc[mi][ni][0]), "+f"(acc[mi][ni][1]),
                          "+f"(acc[mi][ni][2]), "+f"(acc[mi][ni][3])
                        : "r"(afr[mi][0]), "r"(afr[mi][1]),
                          "r"(afr[mi][2]), "r"(afr[mi][3]),
                          "r"(bfr[ni][0]), "r"(bfr[ni][1]));
                }
        }
        __syncthreads();
    }

    // epilogue: fp16 t store + block-local logit reduction
    int head_local = warp >> 2;   // warps 0-3 -> head 0 of block; 4-7 -> head 1
    #pragma unroll
    for (int mi = 0; mi < 4; ++mi) {
        int r0 = m0 + wm + mi * 16 + lr;
        int r1 = r0 + 8;
        float p0 = 0.f, p1 = 0.f;
        #pragma unroll
        for (int ni = 0; ni < 4; ++ni) {
            int cl = wn + ni * 8 + lc * 2;    // block-local col
            int c  = n0 + cl;
            p0 = fmaf(acc[mi][ni][0], s_ar[cl], fmaf(acc[mi][ni][1], s_ar[cl + 1], p0));
            p1 = fmaf(acc[mi][ni][2], s_ar[cl], fmaf(acc[mi][ni][3], s_ar[cl + 1], p1));
            if (r0 < M)
                *(__half2*)&g_th[(size_t)r0 * HO + c] =
                    __floats2half2_rn(acc[mi][ni][0], acc[mi][ni][1]);
            if (r1 < M)
                *(__half2*)&g_th[(size_t)r1 * HO + c] =
                    __floats2half2_rn(acc[mi][ni][2], acc[mi][ni][3]);
        }
        atomicAdd(&s_logit[(wm + mi * 16 + lr    ) * 2 + head_local], p0);
        atomicAdd(&s_logit[(wm + mi * 16 + lr + 8) * 2 + head_local], p1);
    }
    __syncthreads();

    if (tid < 128 && m0 + tid < M) {
        int hb = blockIdx.y * 2;
        g_w[(size_t)(m0 + tid) * HEADS + hb    ] = expf(s_logit[tid * 2 + 0]);
        g_w[(size_t)(m0 + tid) * HEADS + hb + 1] = expf(s_logit[tid * 2 + 1]);
    }
}

// ---------------- aggregation + ELU (fp16 gather, post-normalize) -----------
// One block (128 thr) per node — the empirically fastest structure (R8).
// Thread j owns out[n, 4j..4j+3]; head h = j/16. Column indices staged through
// shared memory with __syncthreads. Segment = [rowptr[n], rowptr[n]+cnt[n]).
// h[n] = (sum_e w_d * t_d) / (sum_e w_d): softmax normalization at the end
// (Al and the max-shift cancel in the ratio).
__global__ __launch_bounds__(128) void k_agg(float* __restrict__ out) {
    __shared__ int s_col[128];

    int n   = blockIdx.x;
    int tid = threadIdx.x;
    int rs  = g_rowptr[n];
    int re  = rs + g_cnt[n];
    int h   = tid >> 4;

    if (re == rs) {  // no outgoing edges: out = elu(0) = 0
        *(float4*)&out[(size_t)n * HO + tid * 4] = make_float4(0.f, 0.f, 0.f, 0.f);
        return;
    }

    float  ws  = 0.f;
    float4 acc = make_float4(0.f, 0.f, 0.f, 0.f);
    const uint2* th2 = (const uint2*)g_th;   // 8 bytes = 4 fp16 per thread

    for (int base = rs; base < re; base += 128) {
        int nload = min(128, re - base);
        __syncthreads();
        if (tid < nload) s_col[tid] = __ldg(&g_col[base + tid]);
        __syncthreads();
        #pragma unroll 4
        for (int e = 0; e < nload; ++e) {
            int d = s_col[e];
            float wv = __ldg(&g_w[(size_t)d * 8 + h]);
            ws += wv;
            uint2 v = th2[(size_t)d * 128 + tid];   // coalesced 1KB row gather
            float2 f0 = __half22float2(*(__half2*)&v.x);
            float2 f1 = __half22float2(*(__half2*)&v.y);
            acc.x = fmaf(wv, f0.x, acc.x);
            acc.y = fmaf(wv, f0.y, acc.y);
            acc.z = fmaf(wv, f1.x, acc.z);
            acc.w = fmaf(wv, f1.y, acc.w);
        }
    }

    float inv = 1.f / ws;
    acc.x *= inv; acc.y *= inv; acc.z *= inv; acc.w *= inv;

    float4 r;
    r.x = acc.x > 0.f ? acc.x : expm1f(acc.x);
    r.y = acc.y > 0.f ? acc.y : expm1f(acc.y);
    r.z = acc.z > 0.f ? acc.z : expm1f(acc.z);
    r.w = acc.w > 0.f ? acc.w : expm1f(acc.w);
    __stcs((float4*)&out[(size_t)n * HO + tid * 4], r);  // stream out, keep t in L2
}

// ---------------- launch ----------------------------------------------------
// CSR build and GEMM are data-independent (CSR: src/dst -> cnt/rowptr/col;
// GEMM: x/Ws/As -> g_th/g_w); only k_agg consumes both. Fork the CSR chain
// onto a second stream inside the capture (event fork/join — the supported
// graph-capture pattern) so ~40us of CSR hides under the ~117us GEMM phase.
// If stream/event creation fails, fall back to fully sequential (identical
// work, identical results).
extern "C" void kernel_launch(void* const* d_in, const int* in_sizes, int n_in,
                              void* d_out, int out_size) {
    const float* x   = (const float*)d_in[0];
    const int*   src = (const int*)  d_in[1];
    const int*   dst = (const int*)  d_in[2];
    const float* Ws  = (const float*)d_in[3];
    const float* As  = (const float*)d_in[4];
    float* out = (float*)d_out;

    int N = in_sizes[0] / IN_F;   // 50000
    int E = in_sizes[1];          // 1600000
    int tE = (E + 3) / 4;

    void* cnt_ptr = nullptr;
    cudaGetSymbolAddress(&cnt_ptr, g_cnt);

    // try to fork a side stream into the capture
    cudaStream_t s2 = 0;
    cudaEvent_t evF = nullptr, evJ = nullptr;
    bool forked = (cudaStreamCreateWithFlags(&s2, cudaStreamNonBlocking) == cudaSuccess);
    if (forked) forked = (cudaEventCreateWithFlags(&evF, cudaEventDisableTiming) == cudaSuccess);
    if (forked) forked = (cudaEventCreateWithFlags(&evJ, cudaEventDisableTiming) == cudaSuccess);

    cudaStream_t sc = forked ? s2 : (cudaStream_t)0;   // CSR stream

    if (forked) {
        cudaEventRecord(evF, 0);            // fork point on the capture stream
        cudaStreamWaitEvent(s2, evF, 0);
    }

    // CSR build (by src): memset(cnt+cursor) -> hist -> fused alloc -> scatter
    cudaMemsetAsync(cnt_ptr, 0, sizeof(int) * (MAXN + 4), sc);
    k_hist<<<(tE + 255) / 256, 256, 0, sc>>>(src, E);
    k_alloc<<<(N + 1023) / 1024, 1024, 0, sc>>>(N);
    k_scatter<<<(tE + 255) / 256, 256, 0, sc>>>(src, dst, E);
    if (forked) cudaEventRecord(evJ, s2);

    // pre-round Ws to tf32 (512 KB, one pass), then fused GEMM + exp(logit)
    k_roundB<<<(HO * IN_F / 4 + 255) / 256, 256>>>(Ws);
    cudaFuncSetAttribute(k_gemm, cudaFuncAttributeMaxDynamicSharedMemorySize,
                         GEMM_SMEM);
    dim3 gg((N + 127) / 128, HO / 128);
    k_gemm<<<gg, 256, GEMM_SMEM>>>(x, As, N);

    if (forked) cudaStreamWaitEvent((cudaStream_t)0, evJ, 0);   // join

    // softmax-weighted aggregation + ELU (one node per block)
    k_agg<<<N, 128>>>(out);
}